// round 16
// baseline (speedup 1.0000x reference)
#include <cuda_runtime.h>
#include <cuda_fp16.h>
#include <cstdint>
#include <cstddef>

// ===================== problem constants =====================
constexpr int B_SZ = 8;
constexpr int N_SZ = 2048;
constexpr int D_SZ = 128;

// ============ GEMM tiling: CTA 64(M) x 128(N) x 64(K), K_IT=32 ============
constexpr int K_IT = 32;
constexpr int A16_STG = 64 * 144;        // 9216 B (64 rows x 72 halves)
constexpr int B_STG = 128 * 144;         // 18432 B (128 rows x 72 halves)
constexpr int B_OFF = 2 * A16_STG;       // A16 ring-2 then B ring-3
constexpr unsigned DYN_B = B_OFF + 3 * B_STG + 256;  // 73984

// h kernel: CTA 64(j) x 128(e), 2 CTAs/SM
constexpr int X32_B = 64 * 128 * 4;              // 32768 fp32 x staging
constexpr int X16_B = 64 * 136 * 2;              // 17408 fp16 x tile (272B rows)
constexpr int W16S_B = 128 * 136 * 2;            // 34816 fp16 W tile
constexpr int X16_OFF = X32_B;
constexpr int W16_OFF = X32_B + X16_B;
constexpr unsigned DYN_H = X32_B + X16_B + W16S_B + 128;  // 85120

// scratch
__device__ __half g_hT[(size_t)B_SZ * D_SZ * N_SZ];  // hT[b][e][j]
__device__ __half g_W16[D_SZ * D_SZ];                // W as fp16

// ===================== helpers =====================
__device__ __forceinline__ uint32_t s2u(const void* p) {
    uint32_t a;
    asm("{ .reg .u64 t; cvta.to.shared.u64 t, %1; cvt.u32.u64 %0, t; }" : "=r"(a) : "l"(p));
    return a;
}
__device__ __forceinline__ void cp16(uint32_t dst, const void* src) {
    asm volatile("cp.async.cg.shared.global [%0], [%1], 16;" :: "r"(dst), "l"(src));
}
__device__ __forceinline__ void mma_f16(float* d, const uint32_t* a,
                                        uint32_t b0, uint32_t b1) {
    asm volatile(
        "mma.sync.aligned.m16n8k16.row.col.f32.f16.f16.f32 "
        "{%0,%1,%2,%3}, {%4,%5,%6,%7}, {%8,%9}, {%0,%1,%2,%3};"
        : "+f"(d[0]), "+f"(d[1]), "+f"(d[2]), "+f"(d[3])
        : "r"(a[0]), "r"(a[1]), "r"(a[2]), "r"(a[3]), "r"(b0), "r"(b1));
}
#define LDSM4(r, addr)                                                          \
    asm volatile("ldmatrix.sync.aligned.m8n8.x4.shared.b16 {%0,%1,%2,%3}, [%4];" \
        : "=r"((r)[0]), "=r"((r)[1]), "=r"((r)[2]), "=r"((r)[3]) : "r"(addr))
__device__ __forceinline__ __half lrelu_h(float x) {
    float v = x > 0.f ? x : 0.01f * x;
    return __float2half_rn(v);
}
__device__ __forceinline__ uint32_t h2u(__half2 h) {
    return *reinterpret_cast<uint32_t*>(&h);
}

// ===================== kernel 0: W -> fp16 (once) =====================
__global__ __launch_bounds__(256) void w16_kernel(const float* __restrict__ W) {
    const int idx = (blockIdx.x * 256 + threadIdx.x) * 8;   // 8 elems/thread
    const float4 v0 = *reinterpret_cast<const float4*>(W + idx);
    const float4 v1 = *reinterpret_cast<const float4*>(W + idx + 4);
    uint4 u;
    u.x = h2u(__floats2half2_rn(v0.x, v0.y));
    u.y = h2u(__floats2half2_rn(v0.z, v0.w));
    u.z = h2u(__floats2half2_rn(v1.x, v1.y));
    u.w = h2u(__floats2half2_rn(v1.z, v1.w));
    *reinterpret_cast<uint4*>(g_W16 + idx) = u;
}

// ===================== kernel 1: hT = fp16(leaky_relu(x @ W^T))^T ===========
// CTA 64(j) x 128(e); x via cp.async fp32 + convert; W16 via cp.async direct
__global__ __launch_bounds__(256, 2) void h_kernel(const float* __restrict__ x) {
    extern __shared__ char hraw[];
    const int tid = threadIdx.x;
    const int b = blockIdx.x >> 5;
    const int j0 = (blockIdx.x & 31) * 64;

    const int wid = tid >> 5;
    const int lane = tid & 31;
    const int g = lane >> 2;
    const int tg = lane & 3;
    const int wm = wid & 1;              // 2 row slices of 32 (j)
    const int wn = wid >> 1;             // 4 col slices of 32 (e)

    const uint32_t base = s2u(hraw);
    const uint32_t x32_u = base;
    const uint32_t x16_u = base + X16_OFF;
    const uint32_t w16_u = base + W16_OFF;
    const float* xg = x + ((size_t)b * N_SZ + j0) * D_SZ;

    // ---- stage: x fp32 (2048 cp16) + W16 fp16 (2048 cp16), fire-and-forget ----
#pragma unroll
    for (int i = 0; i < 8; i++) {
        int c = tid + i * 256;           // 0..2047
        cp16(x32_u + c * 16, xg + c * 4);                    // x linear [64][128] f32
        int e = c >> 4, ch = c & 15;                         // W16 row e, 16B chunk
        cp16(w16_u + e * 272 + ch * 16, g_W16 + e * 128 + ch * 8);
    }
    asm volatile("cp.async.commit_group;" ::: "memory");
    asm volatile("cp.async.wait_group 0;" ::: "memory");
    __syncthreads();

    // ---- convert x fp32 -> fp16 tile (272B rows) ----
    {
        const float4* sx = reinterpret_cast<const float4*>(hraw);
#pragma unroll
        for (int i = 0; i < 8; i++) {
            int c = tid + i * 256;
            int r = c >> 5, q = c & 31;
            float4 v = sx[c];
            uint2 u;
            u.x = h2u(__floats2half2_rn(v.x, v.y));
            u.y = h2u(__floats2half2_rn(v.z, v.w));
            *reinterpret_cast<uint2*>(hraw + X16_OFF + r * 272 + q * 8) = u;
        }
    }
    __syncthreads();

    // ---- MMA: warp tile 32(j) x 32(e), K=128 in 8 ks steps ----
    const uint32_t aAddr0 = x16_u + (uint32_t)((wm * 32 + (lane & 15)) * 272 +
                                               ((lane >> 4) * 16));
    const uint32_t aAddr1 = aAddr0 + 16 * 272;
    const uint32_t bAddr0 = w16_u +
        (uint32_t)((wn * 32 + (lane & 7) + ((lane >> 4) * 8)) * 272 +
                   (((lane >> 3) & 1) * 16));
    const uint32_t bAddr1 = bAddr0 + 16 * 272;

    float acc[2][4][4];
#pragma unroll
    for (int mt = 0; mt < 2; mt++)
#pragma unroll
        for (int nt = 0; nt < 4; nt++)
#pragma unroll
            for (int q = 0; q < 4; q++) acc[mt][nt][q] = 0.f;

#pragma unroll
    for (int ks = 0; ks < 8; ks++) {
        const uint32_t off = ks * 32;
        uint32_t a0[4], a1[4], bf[4], cf[4];
        LDSM4(a0, aAddr0 + off);
        LDSM4(a1, aAddr1 + off);
        LDSM4(bf, bAddr0 + off);
        LDSM4(cf, bAddr1 + off);
        mma_f16(acc[0][0], a0, bf[0], bf[1]);
        mma_f16(acc[0][1], a0, bf[2], bf[3]);
        mma_f16(acc[0][2], a0, cf[0], cf[1]);
        mma_f16(acc[0][3], a0, cf[2], cf[3]);
        mma_f16(acc[1][0], a1, bf[0], bf[1]);
        mma_f16(acc[1][1], a1, bf[2], bf[3]);
        mma_f16(acc[1][2], a1, cf[0], cf[1]);
        mma_f16(acc[1][3], a1, cf[2], cf[3]);
    }
    __syncthreads();                     // x32/x16 regions dead; reuse as transpose buf

    // ---- transpose through smem (hsm[e][j], stride 136 halves) ----
    __half* hsm = reinterpret_cast<__half*>(hraw);   // 128 x 136 halves = 34816 <= 50176
#pragma unroll
    for (int mt = 0; mt < 2; mt++)
#pragma unroll
        for (int nt = 0; nt < 4; nt++) {
            int r = wm * 32 + mt * 16 + g;          // j (0..63)
            int c = wn * 32 + nt * 8 + tg * 2;      // e (0..127)
            hsm[c * 136 + r]           = lrelu_h(acc[mt][nt][0]);
            hsm[(c + 1) * 136 + r]     = lrelu_h(acc[mt][nt][1]);
            hsm[c * 136 + r + 8]       = lrelu_h(acc[mt][nt][2]);
            hsm[(c + 1) * 136 + r + 8] = lrelu_h(acc[mt][nt][3]);
        }
    __syncthreads();

    // ---- store hT: 128 e-rows x 64 j halves (128B/row), 2 threads/row ----
    const int e = tid >> 1;
    const int jh = (tid & 1) * 32;       // 32 halves = 64B
    uint4* dst = reinterpret_cast<uint4*>(g_hT + ((size_t)b * D_SZ + e) * N_SZ + j0 + jh);
    const uint4* src = reinterpret_cast<const uint4*>(hsm + e * 136 + jh);
#pragma unroll
    for (int q = 0; q < 4; q++) dst[q] = src[q];
}

// ===================== kernel 2: fused normalize + An @ h (fp16 MMA) ========
// out[b,i,e] = ( sum_j A[b,i,j] h[b,j,e] + (1 - A[b,i,i]) h[b,i,e] ) / d_i
// d_i = rowsum(A[b,i,:]) - A[b,i,i] + 1
// BK=64: A via LDG->regs (1-iter cover) -> STS fp16 ring-2; B cp.async ring-3
__global__ __launch_bounds__(256, 2) void gcn_gemm_kernel(const float* __restrict__ A,
                                                          const __half* __restrict__ hTg,
                                                          float* __restrict__ out) {
    extern __shared__ float dyn[];
    __shared__ float rs_sm[256];
    __shared__ float corr_sm[64];
    __shared__ float dinv_sm[64];

    const int tid = threadIdx.x;
    const int b = blockIdx.x >> 5;
    const int gi0 = (blockIdx.x & 31) * 64;

    const int wid = tid >> 5;
    const int lane = tid & 31;
    const int g = lane >> 2;
    const int tg = lane & 3;
    const int wm = wid & 1;      // 2 row slices of 32
    const int wn = wid >> 1;     // 4 col slices of 32

    const float* Ag = A + (size_t)b * N_SZ * N_SZ;
    const __half* hTb = hTg + (size_t)b * D_SZ * N_SZ;

    const uint32_t raw = s2u(dyn);
    const uint32_t base_u = (raw + 127u) & ~127u;
    char* dbase = reinterpret_cast<char*>(dyn) + (base_u - raw);

    // A path thread mapping: 4 threads/row, 16 consecutive floats each
    const int arow = tid >> 2;           // 0..63
    const int aq = tid & 3;              // quarter (16 floats)
    float rs = 0.f;

    // ldmatrix lane addresses (row stride 144 B = 72 halves, conflict-free)
    const uint32_t aAddr0 = base_u + (uint32_t)((wm * 32 + (lane & 15)) * 144 +
                                                ((lane >> 4) * 16));
    const uint32_t aAddr1 = aAddr0 + 16 * 144;
    const uint32_t bAddr0 = base_u + B_OFF +
        (uint32_t)((wn * 32 + (lane & 7) + ((lane >> 4) * 8)) * 144 +
                   (((lane >> 3) & 1) * 16));
    const uint32_t bAddr1 = bAddr0 + 16 * 144;

    float4 rv0, rv1, rv2, rv3;           // staged A tile (16 floats/thread)

    auto ldgA = [&](int t) {
        const float* p = Ag + (size_t)(gi0 + arow) * N_SZ + t * 64 + aq * 16;
        rv0 = *reinterpret_cast<const float4*>(p);
        rv1 = *reinterpret_cast<const float4*>(p + 4);
        rv2 = *reinterpret_cast<const float4*>(p + 8);
        rv3 = *reinterpret_cast<const float4*>(p + 12);
    };
    // STS fp16 (2x STS.128) + rowsum from the fp32 staged regs (counted once)
    auto stsA = [&](int slot) {
        uint4 u0, u1;
        u0.x = h2u(__floats2half2_rn(rv0.x, rv0.y));
        u0.y = h2u(__floats2half2_rn(rv0.z, rv0.w));
        u0.z = h2u(__floats2half2_rn(rv1.x, rv1.y));
        u0.w = h2u(__floats2half2_rn(rv1.z, rv1.w));
        u1.x = h2u(__floats2half2_rn(rv2.x, rv2.y));
        u1.y = h2u(__floats2half2_rn(rv2.z, rv2.w));
        u1.z = h2u(__floats2half2_rn(rv3.x, rv3.y));
        u1.w = h2u(__floats2half2_rn(rv3.z, rv3.w));
        uint4* p = reinterpret_cast<uint4*>(dbase + slot * A16_STG + arow * 144 + aq * 32);
        p[0] = u0;
        p[1] = u1;
        rs += ((rv0.x + rv0.y) + (rv0.z + rv0.w)) + ((rv1.x + rv1.y) + (rv1.z + rv1.w)) +
              ((rv2.x + rv2.y) + (rv2.z + rv2.w)) + ((rv3.x + rv3.y) + (rv3.z + rv3.w));
    };
    // B tile t -> given ring slot (128 e-rows x 64 halves, 4 cp16/thread)
    auto cpB = [&](int t, int slot) {
        const uint32_t bb = base_u + B_OFF + slot * B_STG;
#pragma unroll
        for (int i = 0; i < 4; i++) {
            int c2 = tid + i * 256;
            int e = c2 >> 3, ch = c2 & 7;
            cp16(bb + e * 144 + ch * 16,
                 hTb + (size_t)e * N_SZ + t * 64 + ch * 8);
        }
    };

    float acc[2][4][4];
#pragma unroll
    for (int mt = 0; mt < 2; mt++)
#pragma unroll
        for (int nt = 0; nt < 4; nt++)
#pragma unroll
            for (int q = 0; q < 4; q++) acc[mt][nt][q] = 0.f;

    // ---- prologue ----
    ldgA(0);
    cpB(0, 0);
    asm volatile("cp.async.commit_group;" ::: "memory");   // g0 = B0
    cpB(1, 1);
    asm volatile("cp.async.commit_group;" ::: "memory");   // g1 = B1
    stsA(0);                                               // tile0 -> A16 slot0 (one-time stall)
    ldgA(1);

    int sBr = 0, sBw = 2;
    for (int kt = 0; kt < K_IT; kt++) {
        asm volatile("cp.async.wait_group 1;" ::: "memory");  // B(kt) resident (per-thread)
        __syncthreads();                                       // all waits done; old slots dead

        if (kt + 2 < K_IT) cpB(kt + 2, sBw);                   // slot of B(kt-1): dead
        asm volatile("cp.async.commit_group;" ::: "memory");
        if (kt < K_IT - 1) stsA((kt + 1) & 1);                 // tile kt+1 from staged regs
        if (kt + 2 < K_IT) ldgA(kt + 2);                       // refill regs (1-iter cover)

        const uint32_t offA = (uint32_t)(kt & 1) * A16_STG;
        const uint32_t offB = (uint32_t)sBr * B_STG;

#pragma unroll
        for (int ks = 0; ks < 4; ks++) {
            uint32_t a0[4], a1[4], bf[4], cf[4];
            LDSM4(a0, aAddr0 + offA + ks * 32);
            LDSM4(a1, aAddr1 + offA + ks * 32);
            LDSM4(bf, bAddr0 + offB + ks * 32);
            LDSM4(cf, bAddr1 + offB + ks * 32);
            mma_f16(acc[0][0], a0, bf[0], bf[1]);
            mma_f16(acc[0][1], a0, bf[2], bf[3]);
            mma_f16(acc[0][2], a0, cf[0], cf[1]);
            mma_f16(acc[0][3], a0, cf[2], cf[3]);
            mma_f16(acc[1][0], a1, bf[0], bf[1]);
            mma_f16(acc[1][1], a1, bf[2], bf[3]);
            mma_f16(acc[1][2], a1, cf[0], cf[1]);
            mma_f16(acc[1][3], a1, cf[2], cf[3]);
        }
        sBr = (sBr == 2) ? 0 : sBr + 1;
        sBw = (sBw == 2) ? 0 : sBw + 1;
    }

    // ---- reductions & epilogue ----
    rs_sm[tid] = rs;
    __syncthreads();                    // all compute done, rings dead

    if (tid < 64) {
        const float* srcp = rs_sm + tid * 4;
        float d = (srcp[0] + srcp[1]) + (srcp[2] + srcp[3]);
        float aii = Ag[(size_t)(gi0 + tid) * (N_SZ + 1)];
        float c = 1.0f - aii;           // mask true: A>=0, rows strictly positive
        corr_sm[tid] = c;
        dinv_sm[tid] = 1.0f / (d + c);
    }

    float* o_sm = reinterpret_cast<float*>(dbase);            // [64][132] f32 (33792 B)
    float* hf = reinterpret_cast<float*>(dbase) + 64 * 132;   // [128][65] f32 (33280 B)
#pragma unroll
    for (int mt = 0; mt < 2; mt++)
#pragma unroll
        for (int nt = 0; nt < 4; nt++) {
            int r = wm * 32 + mt * 16 + g;
            int c = wn * 32 + nt * 8 + tg * 2;
            o_sm[r * 132 + c]           = acc[mt][nt][0];
            o_sm[r * 132 + c + 1]       = acc[mt][nt][1];
            o_sm[(r + 8) * 132 + c]     = acc[mt][nt][2];
            o_sm[(r + 8) * 132 + c + 1] = acc[mt][nt][3];
        }

    // load hT[:, gi0..gi0+64) tile -> float smem (for diag correction)
    {
        const int e = tid >> 1;
        const int part = tid & 1;
        const uint4* src = reinterpret_cast<const uint4*>(
            hTb + (size_t)e * N_SZ + gi0 + part * 32);
#pragma unroll
        for (int q = 0; q < 4; q++) {
            uint4 v = src[q];
            uint32_t w[4] = {v.x, v.y, v.z, v.w};
#pragma unroll
            for (int u = 0; u < 4; u++) {
                float2 f = __half22float2(*reinterpret_cast<__half2*>(&w[u]));
                hf[e * 65 + part * 32 + q * 8 + u * 2]     = f.x;
                hf[e * 65 + part * 32 + q * 8 + u * 2 + 1] = f.y;
            }
        }
    }
    __syncthreads();

    float* ob = out + ((size_t)b * N_SZ + gi0) * D_SZ;
#pragma unroll 8
    for (int i = tid; i < 64 * 128; i += 256) {
        int r = i >> 7, e = i & 127;
        ob[i] = (o_sm[r * 132 + e] + corr_sm[r] * hf[e * 65 + r]) * dinv_sm[r];
    }
}

// ===================== host =====================
extern "C" void kernel_launch(void* const* d_in, const int* in_sizes, int n_in,
                              void* d_out, int out_size) {
    const float* x = (const float*)d_in[0];
    const float* A = (const float*)d_in[1];
    const float* W = (const float*)d_in[2];
    float* out = (float*)d_out;

    void* hT_ptr = nullptr;
    cudaGetSymbolAddress(&hT_ptr, g_hT);

    w16_kernel<<<D_SZ * D_SZ / (256 * 8), 256>>>(W);

    cudaFuncSetAttribute(h_kernel, cudaFuncAttributeMaxDynamicSharedMemorySize, DYN_H);
    h_kernel<<<B_SZ * (N_SZ / 64), 256, DYN_H>>>(x);

    cudaFuncSetAttribute(gcn_gemm_kernel, cudaFuncAttributeMaxDynamicSharedMemorySize, DYN_B);
    gcn_gemm_kernel<<<B_SZ * (N_SZ / 64), 256, DYN_B>>>(A, (const __half*)hT_ptr, out);
    (void)in_sizes; (void)n_in; (void)out_size;
}